// round 14
// baseline (speedup 1.0000x reference)
#include <cuda_runtime.h>
#include <cuda_fp16.h>
#include <cstdint>
#include <cstddef>

// ---------------- problem constants ----------------
#define L_DIM 1024
#define B_DIM 16
#define NIN   1024
#define NOUT  512
#define MDIM  16384            // L*B
#define NGEMM 2560             // NOUT*5
#define KGEMM 1024

// ---------------- GEMM tiling ----------------
#define BM 128
#define BN 128
#define KSTAGE 64
#define NSTAGES 3
#define KT (KGEMM / KSTAGE)                 // 16
#define A_BYTES (BM * KSTAGE * 2)           // 16384
#define B_BYTES (BN * KSTAGE * 2)           // 16384
#define STAGE_BYTES (A_BYTES + B_BYTES)     // 32768
#define SMEM_DYN (NSTAGES * STAGE_BYTES)    // 98304
#define NTHREADS 256
#define NTILE_M (MDIM / BM)                 // 128
#define NTILE_N (NGEMM / BN)                // 20
#define NTILES  (NTILE_M * NTILE_N)         // 2560
#define GRID_CTAS 296                       // 2/SM x 148 SMs, all resident

// ---------------- scan chunking ----------------
#define NCH   16
#define CLEN  (L_DIM / NCH)                 // 64
#define NLANE 8192                          // B*NOUT
#define NCOL  (NLANE / 256)                 // 32 lane-columns

// queue: per chunk group = 160 GEMM tiles + 32 scan items; finals appended
#define GROUP_ITEMS (160 + NCOL)            // 192
#define NITEMS (NCH * GROUP_ITEMS + NCOL)   // 3104

// ---------------- scratch (static, no allocation) ----------------
__device__ __half g_Uh[(size_t)MDIM * NGEMM];   // 80 MB packed fp16 activations
__device__ uint4 g_Xh[(size_t)(MDIM / 16) * (KGEMM / 16) * 32];   // 32 MB A-frag
__device__ uint4 g_Wh[(size_t)(NGEMM / 8) * (KGEMM / 32) * 32];   // 5 MB B-frag
__device__ float g_coef[NCH * 5 * NLANE];       // per-chunk transfer coefficients
__device__ int   g_next;                        // work-queue cursor
__device__ int   g_chunk_cnt[NCH];              // tiles completed per l-chunk
__device__ int   g_mask[NCOL];                  // per-column coef-ready bitmask

__device__ __forceinline__ float sigmoidf_fast(float x) {
    return 1.0f / (1.0f + __expf(-x));
}
__device__ __forceinline__ uint32_t h2u(float lo, float hi) {
    __half2 h = __floats2half2_rn(lo, hi);
    return *reinterpret_cast<uint32_t*>(&h);
}
__device__ __forceinline__ uint32_t smem_u32(const void* p) {
    return (uint32_t)__cvta_generic_to_shared(p);
}
__device__ __forceinline__ void cp_async16(uint32_t dst, const void* src) {
    asm volatile("cp.async.cg.shared.global [%0], [%1], 16;\n" :: "r"(dst), "l"(src));
}
__device__ __forceinline__ void mma_f16(float4& d, uint4 a, uint32_t b0, uint32_t b1) {
    asm volatile(
        "mma.sync.aligned.m16n8k16.row.col.f32.f16.f16.f32 "
        "{%0,%1,%2,%3}, {%4,%5,%6,%7}, {%8,%9}, {%0,%1,%2,%3};"
        : "+f"(d.x), "+f"(d.y), "+f"(d.z), "+f"(d.w)
        : "r"(a.x), "r"(a.y), "r"(a.z), "r"(a.w), "r"(b0), "r"(b1));
}

// ---------------------------------------------------------------------------
// prep_kernel: fused preround + permw; block 0 resets queue/sync state.
// ---------------------------------------------------------------------------
__global__ void __launch_bounds__(256)
prep_kernel(const float* __restrict__ x, const float* __restrict__ w) {
    const int tid = threadIdx.x;
    if (blockIdx.x == 0) {
        if (tid == 0) g_next = 0;
        if (tid < NCH)  g_chunk_cnt[tid] = 0;
        if (tid < NCOL) g_mask[tid] = 0;
    }
    if (blockIdx.x < 8192) {
        __shared__ float sm[16][132];
        const int r16  = blockIdx.x >> 3;
        const int kblk = blockIdx.x & 7;
#pragma unroll
        for (int i = 0; i < 2; i++) {
            int t = i * 256 + tid;
            int row = t >> 5, c4 = t & 31;
            float4 v = *(const float4*)(x + (size_t)(r16 * 16 + row) * KGEMM + kblk * 128 + c4 * 4);
            sm[row][c4 * 4 + 0] = v.x; sm[row][c4 * 4 + 1] = v.y;
            sm[row][c4 * 4 + 2] = v.z; sm[row][c4 * 4 + 3] = v.w;
        }
        __syncthreads();

        int k16l = tid >> 5, lane = tid & 31;
        int g = lane >> 2, tg = lane & 3;
        int c0 = k16l * 16 + tg * 2;
        uint4 o;
        o.x = h2u(sm[g][c0],         sm[g][c0 + 1]);
        o.y = h2u(sm[g + 8][c0],     sm[g + 8][c0 + 1]);
        o.z = h2u(sm[g][c0 + 8],     sm[g][c0 + 9]);
        o.w = h2u(sm[g + 8][c0 + 8], sm[g + 8][c0 + 9]);
        g_Xh[((size_t)r16 * 64 + kblk * 8 + k16l) * 32 + lane] = o;
    } else {
        int t = (blockIdx.x - 8192) * 256 + tid;
        int lane = t & 31;
        int chunk = t >> 5;
        int k32 = chunk & 31, n8 = chunk >> 5;
        int g = lane >> 2, tg = lane & 3;
        int j2 = n8 * 8 + g;
        int j  = (j2 < 2048) ? ((j2 >> 2) * 5 + (j2 & 3)) : ((j2 - 2048) * 5 + 4);
        int k0 = k32 * 32;
        uint4 o;
        o.x = h2u(w[(size_t)(k0 + 2 * tg)      * NGEMM + j], w[(size_t)(k0 + 2 * tg + 1)  * NGEMM + j]);
        o.y = h2u(w[(size_t)(k0 + 2 * tg + 8)  * NGEMM + j], w[(size_t)(k0 + 2 * tg + 9)  * NGEMM + j]);
        o.z = h2u(w[(size_t)(k0 + 2 * tg + 16) * NGEMM + j], w[(size_t)(k0 + 2 * tg + 17) * NGEMM + j]);
        o.w = h2u(w[(size_t)(k0 + 2 * tg + 24) * NGEMM + j], w[(size_t)(k0 + 2 * tg + 25) * NGEMM + j]);
        g_Wh[(size_t)t] = o;
    }
}

// ---------------------------------------------------------------------------
// Mega kernel: 296 persistent CTAs pop from a chunk-major work queue.
// Items per chunk ch: 160 GEMM tiles (m-tiles ch*8..ch*8+7 x 20 n-tiles),
// then 32 scan items (one per lane column). 32 finals items at the end.
// ---------------------------------------------------------------------------
__global__ void __launch_bounds__(NTHREADS, 2)
mega_kernel(const float* __restrict__ bias, const float* __restrict__ bias_eps,
            const float* __restrict__ bias_final, float* __restrict__ out) {
    extern __shared__ char smraw[];
    __shared__ int s_item;
    const uint32_t sbase = smem_u32(smraw);

    const int tid = threadIdx.x;
    const int wid = tid >> 5, lane = tid & 31;
    const int gid = lane >> 2, tig = lane & 3;
    const int wm = wid >> 1, wn = wid & 1;       // 4 x 2 warps

    for (;;) {
        if (tid == 0) s_item = atomicAdd(&g_next, 1);
        __syncthreads();
        const int item = s_item;
        __syncthreads();
        if (item >= NITEMS) return;

        int group = -1, within = 0;
        if (item < NCH * GROUP_ITEMS) { group = item / GROUP_ITEMS; within = item % GROUP_ITEMS; }

        if (group >= 0 && within < 160) {
            // ================= GEMM tile =================
            const int m0 = (group * 8 + within / NTILE_N) * BM;
            const int n0 = (within % NTILE_N) * BN;

            float4 acc[2][8];
#pragma unroll
            for (int i = 0; i < 2; i++)
#pragma unroll
                for (int j = 0; j < 8; j++) acc[i][j] = make_float4(0.f, 0.f, 0.f, 0.f);

            auto load_stage = [&](int s) {
                uint32_t sb = sbase + (uint32_t)(s % NSTAGES) * STAGE_BYTES;
#pragma unroll
                for (int i = 0; i < 8; i++) {
                    int t = i * NTHREADS + tid;           // 0..2047
                    if (t < 1024) {                       // A: chunk = r16l*4 + k16l
                        int chunk = t >> 5, ln = t & 31;
                        int r16l = chunk >> 2, k16l = chunk & 3;
                        const uint4* src = g_Xh +
                            ((size_t)((m0 >> 4) + r16l) * 64 + (s * 4 + k16l)) * 32 + ln;
                        cp_async16(sb + t * 16, src);
                    } else {                              // B: chunk = n8l*2 + k32l
                        int jdx = t - 1024;
                        int chunk = jdx >> 5, ln = jdx & 31;
                        int n8l = chunk >> 1, k32l = chunk & 1;
                        const uint4* src = g_Wh +
                            ((size_t)((n0 >> 3) + n8l) * 32 + (s * 2 + k32l)) * 32 + ln;
                        cp_async16(sb + A_BYTES + jdx * 16, src);
                    }
                }
                asm volatile("cp.async.commit_group;");
            };

            load_stage(0); load_stage(1);

            for (int s = 0; s < KT; ++s) {
                if (s < KT - 1) asm volatile("cp.async.wait_group 1;");
                else            asm volatile("cp.async.wait_group 0;");
                __syncthreads();
                if (s + 2 < KT) load_stage(s + 2);

                const char* As = smraw + (size_t)(s % NSTAGES) * STAGE_BYTES;
                const char* Bs = As + A_BYTES;

#pragma unroll
                for (int k32 = 0; k32 < 2; k32++) {
                    uint4 a[2][2];
#pragma unroll
                    for (int im = 0; im < 2; im++)
#pragma unroll
                        for (int k16 = 0; k16 < 2; k16++)
                            a[im][k16] = *(const uint4*)(As +
                                (((wm * 2 + im) * 4 + k32 * 2 + k16) * 32 + lane) * 16);

#pragma unroll
                    for (int jh = 0; jh < 2; jh++) {
                        uint4 b[4];
#pragma unroll
                        for (int j = 0; j < 4; j++)
                            b[j] = *(const uint4*)(Bs +
                                (((wn * 8 + jh * 4 + j) * 2 + k32) * 32 + lane) * 16);
#pragma unroll
                        for (int j = 0; j < 4; j++)
#pragma unroll
                            for (int im = 0; im < 2; im++)
                                mma_f16(acc[im][jh * 4 + j], a[im][0], b[j].x, b[j].y);
#pragma unroll
                        for (int j = 0; j < 4; j++)
#pragma unroll
                            for (int im = 0; im < 2; im++)
                                mma_f16(acc[im][jh * 4 + j], a[im][1], b[j].z, b[j].w);
                    }
                }
            }

            // epilogue: transform + direct half2 stores
#pragma unroll
            for (int im = 0; im < 2; im++) {
                const int row = m0 + wm * 32 + im * 16 + gid;
                __half* r0p = g_Uh + (size_t)row * NGEMM;
                __half* r1p = g_Uh + (size_t)(row + 8) * NGEMM;
#pragma unroll
                for (int jn = 0; jn < 8; jn++) {
                    const int col = n0 + wn * 64 + jn * 8 + tig * 2;
                    float4 c = acc[im][jn];
                    if (col >= 2048) {
                        float b0 = __ldg(&bias[col]);
                        float b1 = __ldg(&bias[col + 1]);
                        c.x = sigmoidf_fast(c.x + b0); c.y = sigmoidf_fast(c.y + b1);
                        c.z = sigmoidf_fast(c.z + b0); c.w = sigmoidf_fast(c.w + b1);
                    } else if (col & 2) {
                        int n = col >> 2;
                        float b0 = __ldg(&bias[1024 + n]);
                        float b1 = __ldg(&bias[1536 + n]);
                        c.x = sigmoidf_fast(c.x + b0); c.y = sigmoidf_fast(c.y + b1);
                        c.z = sigmoidf_fast(c.z + b0); c.w = sigmoidf_fast(c.w + b1);
                    }
                    *(__half2*)(r0p + col) = __floats2half2_rn(c.x, c.y);
                    *(__half2*)(r1p + col) = __floats2half2_rn(c.z, c.w);
                }
            }
            __syncthreads();                   // all stores issued
            if (tid == 0) {
                __threadfence();               // release
                atomicAdd(&g_chunk_cnt[m0 >> 10], 1);
            }
        } else {
            // ================= scan / finals item =================
            const int xcol = (group >= 0) ? (within - 160) : (item - NCH * GROUP_ITEMS);
            const int ch   = (group >= 0) ? group : NCH;
            const int lane2 = xcol * 256 + tid;
            const int n = lane2 & (NOUT - 1);
            const int b = lane2 >> 9;

            float eps = sigmoidf_fast(__ldg(&bias_eps[n]));

            if (ch < NCH) {
                // wait for this chunk's 160 GEMM tiles
                if (tid == 0) {
                    while (atomicAdd(&g_chunk_cnt[ch], 0) < 160) { }
                }
                __syncthreads();
                __threadfence();               // acquire

                // compute transfer coefficients for chunk ch
                float a1 = 1.f, b1 = 0.f, P = 1.f, Q = 0.f, R = 0.f;
                const uint2* qp = reinterpret_cast<const uint2*>(g_Uh) +
                                  (size_t)(ch * CLEN * 16 + b) * 640 + n;
#pragma unroll 4
                for (int l = 0; l < CLEN; ++l) {
                    uint2 q = __ldg(qp);
                    float2 u = __half22float2(*reinterpret_cast<__half2*>(&q.x));
                    float2 f = __half22float2(*reinterpret_cast<__half2*>(&q.y));
                    Q = fmaf(Q, f.y, a1 * u.y);
                    R = fmaf(R, f.y, (eps + b1) * u.y);
                    P = P * f.y;
                    b1 = fmaf(b1, f.x, u.x);
                    a1 = a1 * f.x;
                    qp += 16 * 640;
                }
                g_coef[(ch * 5 + 0) * NLANE + lane2] = a1;
                g_coef[(ch * 5 + 1) * NLANE + lane2] = b1;
                g_coef[(ch * 5 + 2) * NLANE + lane2] = P;
                g_coef[(ch * 5 + 3) * NLANE + lane2] = Q;
                g_coef[(ch * 5 + 4) * NLANE + lane2] = R;
                __syncthreads();
                __threadfence();
                if (tid == 0) atomicOr(&g_mask[xcol], 1 << ch);
            }

            // wait for prerequisite chunks of this column
            const int need = (ch >= NCH) ? ((1 << NCH) - 1) : ((1 << ch) - 1);
            if (need) {
                if (tid == 0) {
                    while ((atomicOr(&g_mask[xcol], 0) & need) != need) { }
                }
                __syncthreads();
                __threadfence();               // acquire
            }

            // prologue: chain carries through chunks < ch
            float c1 = 0.f, c2 = 0.f;
            for (int k = 0; k < ch && k < NCH; ++k) {
                float a1 = g_coef[(k * 5 + 0) * NLANE + lane2];
                float b1 = g_coef[(k * 5 + 1) * NLANE + lane2];
                float P  = g_coef[(k * 5 + 2) * NLANE + lane2];
                float Q  = g_coef[(k * 5 + 3) * NLANE + lane2];
                float R  = g_coef[(k * 5 + 4) * NLANE + lane2];
                float c2n = fmaf(P, c2, fmaf(Q, c1, R));
                c1 = fmaf(a1, c1, b1);
                c2 = c2n;
            }

            if (ch == NCH) {   // finals item
                const size_t GCS = (size_t)L_DIM * B_DIM * NOUT;
                out[GCS + lane2]        = c1;
                out[GCS + 8192 + lane2] = c2;
            } else {
                float rho0 = 2.0f * sigmoidf_fast(__ldg(&bias_final[2 * n]));
                float rho1 = 2.0f * sigmoidf_fast(__ldg(&bias_final[2 * n + 1]));

                const uint2*  qp  = reinterpret_cast<const uint2*>(g_Uh) +
                                    (size_t)(ch * CLEN * 16 + b) * 640 + n;
                const __half* ogp = g_Uh + (size_t)(ch * CLEN * 16 + b) * 2560 + 2048 + n;
                float*        gp  = out + (size_t)ch * CLEN * NLANE + lane2;

#pragma unroll 4
                for (int l = 0; l < CLEN; ++l) {
                    uint2 q = __ldg(qp);
                    float2 u = __half22float2(*reinterpret_cast<__half2*>(&q.x));
                    float2 f = __half22float2(*reinterpret_cast<__half2*>(&q.y));
                    float og = __half2float(__ldg(ogp));
                    float c1n = fmaf(c1, f.x, u.x);
                    float c2n = fmaf(c2, f.y, (eps + c1) * u.y);
                    c1 = c1n; c2 = c2n;
                    float t = og * (c1 * rho0 + c2 * rho1);
                    float r;
                    asm("tanh.approx.f32 %0, %1;" : "=f"(r) : "f"(t));
                    *gp = r;
                    qp  += 16 * 640;
                    ogp += 16 * 2560;
                    gp  += NLANE;
                }
            }
            __syncthreads();
        }
    }
}

// ---------------------------------------------------------------------------
extern "C" void kernel_launch(void* const* d_in, const int* in_sizes, int n_in,
                              void* d_out, int out_size) {
    (void)in_sizes; (void)n_in; (void)out_size;
    const float* x          = (const float*)d_in[0];
    const float* weight     = (const float*)d_in[1];
    const float* bias       = (const float*)d_in[2];
    const float* bias_eps   = (const float*)d_in[3];
    const float* bias_final = (const float*)d_in[4];
    float* out = (float*)d_out;

    cudaFuncSetAttribute(mega_kernel, cudaFuncAttributeMaxDynamicSharedMemorySize, SMEM_DYN);

    prep_kernel<<<8192 + 1280, 256>>>(x, weight);
    mega_kernel<<<GRID_CTAS, NTHREADS, SMEM_DYN>>>(bias, bias_eps, bias_final, out);
}

// round 15
// speedup vs baseline: 1.4574x; 1.4574x over previous
#include <cuda_runtime.h>
#include <cuda_fp16.h>
#include <cstdint>
#include <cstddef>

// ---------------- problem constants ----------------
#define L_DIM 1024
#define B_DIM 16
#define NIN   1024
#define NOUT  512
#define MDIM  16384            // L*B
#define NGEMM 2560             // NOUT*5
#define KGEMM 1024

// ---------------- GEMM tiling ----------------
#define BM 128
#define BN 128
#define KSTAGE 64
#define NSTAGES 3
#define KT (KGEMM / KSTAGE)                 // 16
#define A_BYTES (BM * KSTAGE * 2)           // 16384
#define B_BYTES (BN * KSTAGE * 2)           // 16384
#define STAGE_BYTES (A_BYTES + B_BYTES)     // 32768
#define SMEM_DYN (NSTAGES * STAGE_BYTES)    // 98304
#define NTHREADS 256

// ---------------- scan chunking ----------------
#define NCH   32
#define CLEN  (L_DIM / NCH)                 // 32
#define NLANE 8192                          // B*NOUT

// ---------------- scratch (static, no allocation) ----------------
__device__ __half g_Uh[(size_t)MDIM * NGEMM];   // 80 MB packed fp16 activations
__device__ uint4 g_Xh[(size_t)(MDIM / 16) * (KGEMM / 16) * 32];   // 32 MB A-frag
__device__ uint4 g_Wh[(size_t)(NGEMM / 8) * (KGEMM / 32) * 32];   // 5 MB B-frag
__device__ float g_coef[NCH * 5 * NLANE];       // per-chunk transfer coefficients

__device__ __forceinline__ float sigmoidf_fast(float x) {
    return 1.0f / (1.0f + __expf(-x));
}
__device__ __forceinline__ uint32_t h2u(float lo, float hi) {
    __half2 h = __floats2half2_rn(lo, hi);
    return *reinterpret_cast<uint32_t*>(&h);
}
__device__ __forceinline__ uint32_t smem_u32(const void* p) {
    return (uint32_t)__cvta_generic_to_shared(p);
}
__device__ __forceinline__ void cp_async16(uint32_t dst, const void* src) {
    asm volatile("cp.async.cg.shared.global [%0], [%1], 16;\n" :: "r"(dst), "l"(src));
}
__device__ __forceinline__ void mma_f16(float4& d, uint4 a, uint32_t b0, uint32_t b1) {
    asm volatile(
        "mma.sync.aligned.m16n8k16.row.col.f32.f16.f16.f32 "
        "{%0,%1,%2,%3}, {%4,%5,%6,%7}, {%8,%9}, {%0,%1,%2,%3};"
        : "+f"(d.x), "+f"(d.y), "+f"(d.z), "+f"(d.w)
        : "r"(a.x), "r"(a.y), "r"(a.z), "r"(a.w), "r"(b0), "r"(b1));
}

// ---------------------------------------------------------------------------
// prep_kernel: fused preround (blocks 0..8191) + permw (blocks 8192..9471)
// ---------------------------------------------------------------------------
__global__ void __launch_bounds__(256)
prep_kernel(const float* __restrict__ x, const float* __restrict__ w) {
    const int tid = threadIdx.x;
    if (blockIdx.x < 8192) {
        __shared__ float sm[16][132];
        const int r16  = blockIdx.x >> 3;
        const int kblk = blockIdx.x & 7;
#pragma unroll
        for (int i = 0; i < 2; i++) {
            int t = i * 256 + tid;
            int row = t >> 5, c4 = t & 31;
            float4 v = *(const float4*)(x + (size_t)(r16 * 16 + row) * KGEMM + kblk * 128 + c4 * 4);
            sm[row][c4 * 4 + 0] = v.x; sm[row][c4 * 4 + 1] = v.y;
            sm[row][c4 * 4 + 2] = v.z; sm[row][c4 * 4 + 3] = v.w;
        }
        __syncthreads();

        int k16l = tid >> 5, lane = tid & 31;
        int g = lane >> 2, tg = lane & 3;
        int c0 = k16l * 16 + tg * 2;
        uint4 o;
        o.x = h2u(sm[g][c0],         sm[g][c0 + 1]);
        o.y = h2u(sm[g + 8][c0],     sm[g + 8][c0 + 1]);
        o.z = h2u(sm[g][c0 + 8],     sm[g][c0 + 9]);
        o.w = h2u(sm[g + 8][c0 + 8], sm[g + 8][c0 + 9]);
        g_Xh[((size_t)r16 * 64 + kblk * 8 + k16l) * 32 + lane] = o;
    } else {
        int t = (blockIdx.x - 8192) * 256 + tid;
        int lane = t & 31;
        int chunk = t >> 5;
        int k32 = chunk & 31, n8 = chunk >> 5;
        int g = lane >> 2, tg = lane & 3;
        int j2 = n8 * 8 + g;
        int j  = (j2 < 2048) ? ((j2 >> 2) * 5 + (j2 & 3)) : ((j2 - 2048) * 5 + 4);
        int k0 = k32 * 32;
        uint4 o;
        o.x = h2u(w[(size_t)(k0 + 2 * tg)      * NGEMM + j], w[(size_t)(k0 + 2 * tg + 1)  * NGEMM + j]);
        o.y = h2u(w[(size_t)(k0 + 2 * tg + 8)  * NGEMM + j], w[(size_t)(k0 + 2 * tg + 9)  * NGEMM + j]);
        o.z = h2u(w[(size_t)(k0 + 2 * tg + 16) * NGEMM + j], w[(size_t)(k0 + 2 * tg + 17) * NGEMM + j]);
        o.w = h2u(w[(size_t)(k0 + 2 * tg + 24) * NGEMM + j], w[(size_t)(k0 + 2 * tg + 25) * NGEMM + j]);
        g_Wh[(size_t)t] = o;
    }
}

// ---------------------------------------------------------------------------
// fp16 mma.sync GEMM: 128x128 tile, 8 warps (4x2), warp tile 32x64, 2 CTAs/SM.
// KSTAGE=64, 3-stage ring, direct half2 epilogue stores (R11 form).
// ---------------------------------------------------------------------------
__global__ void __launch_bounds__(NTHREADS, 2)
gemm_kernel(const float* __restrict__ bias) {
    extern __shared__ char smraw[];
    const uint32_t sbase = smem_u32(smraw);

    const int tid = threadIdx.x;
    const int wid = tid >> 5, lane = tid & 31;
    const int gid = lane >> 2, tig = lane & 3;
    const int wm = wid >> 1, wn = wid & 1;       // 4 x 2 warps
    const int m0 = blockIdx.y * BM;
    const int n0 = blockIdx.x * BN;

    float4 acc[2][8];
#pragma unroll
    for (int i = 0; i < 2; i++)
#pragma unroll
        for (int j = 0; j < 8; j++) acc[i][j] = make_float4(0.f, 0.f, 0.f, 0.f);

    auto load_stage = [&](int s) {
        uint32_t sb = sbase + (uint32_t)(s % NSTAGES) * STAGE_BYTES;
#pragma unroll
        for (int i = 0; i < 8; i++) {
            int t = i * NTHREADS + tid;           // 0..2047
            if (t < 1024) {                       // A: chunk = r16l*4 + k16l
                int chunk = t >> 5, ln = t & 31;
                int r16l = chunk >> 2, k16l = chunk & 3;
                const uint4* src = g_Xh +
                    ((size_t)((m0 >> 4) + r16l) * 64 + (s * 4 + k16l)) * 32 + ln;
                cp_async16(sb + t * 16, src);
            } else {                              // B: chunk = n8l*2 + k32l
                int jdx = t - 1024;
                int chunk = jdx >> 5, ln = jdx & 31;
                int n8l = chunk >> 1, k32l = chunk & 1;
                const uint4* src = g_Wh +
                    ((size_t)((n0 >> 3) + n8l) * 32 + (s * 2 + k32l)) * 32 + ln;
                cp_async16(sb + A_BYTES + jdx * 16, src);
            }
        }
        asm volatile("cp.async.commit_group;");
    };

    load_stage(0); load_stage(1);

    for (int s = 0; s < KT; ++s) {
        if (s < KT - 1) asm volatile("cp.async.wait_group 1;");
        else            asm volatile("cp.async.wait_group 0;");
        __syncthreads();
        if (s + 2 < KT) load_stage(s + 2);

        const char* As = smraw + (size_t)(s % NSTAGES) * STAGE_BYTES;
        const char* Bs = As + A_BYTES;

#pragma unroll
        for (int k32 = 0; k32 < 2; k32++) {
            uint4 a[2][2];
#pragma unroll
            for (int im = 0; im < 2; im++)
#pragma unroll
                for (int k16 = 0; k16 < 2; k16++)
                    a[im][k16] = *(const uint4*)(As +
                        (((wm * 2 + im) * 4 + k32 * 2 + k16) * 32 + lane) * 16);

#pragma unroll
            for (int jh = 0; jh < 2; jh++) {
                uint4 b[4];
#pragma unroll
                for (int j = 0; j < 4; j++)
                    b[j] = *(const uint4*)(Bs +
                        (((wn * 8 + jh * 4 + j) * 2 + k32) * 32 + lane) * 16);
#pragma unroll
                for (int j = 0; j < 4; j++)
#pragma unroll
                    for (int im = 0; im < 2; im++)
                        mma_f16(acc[im][jh * 4 + j], a[im][0], b[j].x, b[j].y);
#pragma unroll
                for (int j = 0; j < 4; j++)
#pragma unroll
                    for (int im = 0; im < 2; im++)
                        mma_f16(acc[im][jh * 4 + j], a[im][1], b[j].z, b[j].w);
            }
        }
    }

    // ---- epilogue: transform + direct half2 stores ----
#pragma unroll
    for (int im = 0; im < 2; im++) {
        const int row = m0 + wm * 32 + im * 16 + gid;
        __half* r0p = g_Uh + (size_t)row * NGEMM;
        __half* r1p = g_Uh + (size_t)(row + 8) * NGEMM;
#pragma unroll
        for (int jn = 0; jn < 8; jn++) {
            const int col = n0 + wn * 64 + jn * 8 + tig * 2;
            float4 c = acc[im][jn];
            if (col >= 2048) {
                float b0 = __ldg(&bias[col]);
                float b1 = __ldg(&bias[col + 1]);
                c.x = sigmoidf_fast(c.x + b0); c.y = sigmoidf_fast(c.y + b1);
                c.z = sigmoidf_fast(c.z + b0); c.w = sigmoidf_fast(c.w + b1);
            } else if (col & 2) {
                int n = col >> 2;
                float b0 = __ldg(&bias[1024 + n]);
                float b1 = __ldg(&bias[1536 + n]);
                c.x = sigmoidf_fast(c.x + b0); c.y = sigmoidf_fast(c.y + b1);
                c.z = sigmoidf_fast(c.z + b0); c.w = sigmoidf_fast(c.w + b1);
            }
            *(__half2*)(r0p + col) = __floats2half2_rn(c.x, c.y);
            *(__half2*)(r1p + col) = __floats2half2_rn(c.z, c.w);
        }
    }
}

// ---------------------------------------------------------------------------
// Scan pass 1: per-(lane, chunk) transfer coefficients (fp16 in, fp32 math)
//   c1(t) = a1*c1_0 + b1 ;  c2(t) = P*c2_0 + Q*c1_0 + R
// ---------------------------------------------------------------------------
__global__ void __launch_bounds__(256)
scan_pass1(const float* __restrict__ bias_eps) {
    int lane = blockIdx.x * 256 + threadIdx.x;
    int ch   = blockIdx.y;
    int n = lane & (NOUT - 1);
    int b = lane >> 9;

    float eps = sigmoidf_fast(__ldg(&bias_eps[n]));

    float a1 = 1.f, b1 = 0.f, P = 1.f, Q = 0.f, R = 0.f;

    const uint2* qp = reinterpret_cast<const uint2*>(g_Uh) +
                      (size_t)(ch * CLEN * 16 + b) * 640 + n;

#pragma unroll 4
    for (int l = 0; l < CLEN; ++l) {
        uint2 q = __ldg(qp);
        float2 u = __half22float2(*reinterpret_cast<__half2*>(&q.x));
        float2 f = __half22float2(*reinterpret_cast<__half2*>(&q.y));
        Q = fmaf(Q, f.y, a1 * u.y);
        R = fmaf(R, f.y, (eps + b1) * u.y);
        P = P * f.y;
        b1 = fmaf(b1, f.x, u.x);
        a1 = a1 * f.x;
        qp += 16 * 640;
    }
    g_coef[(ch * 5 + 0) * NLANE + lane] = a1;
    g_coef[(ch * 5 + 1) * NLANE + lane] = b1;
    g_coef[(ch * 5 + 2) * NLANE + lane] = P;
    g_coef[(ch * 5 + 3) * NLANE + lane] = Q;
    g_coef[(ch * 5 + 4) * NLANE + lane] = R;
}

// ---------------------------------------------------------------------------
// Scan pass 2 (combine fused): prologue chains g_coef over chunks < ch,
// then replays the chunk. Row ch == NCH writes the final carries only.
// ---------------------------------------------------------------------------
__global__ void __launch_bounds__(256)
scan_pass2(const float* __restrict__ bias_eps, const float* __restrict__ bias_final,
           float* __restrict__ out) {
    int lane = blockIdx.x * 256 + threadIdx.x;
    int ch   = blockIdx.y;           // 0..NCH
    int n = lane & (NOUT - 1);
    int b = lane >> 9;

    float c1 = 0.f, c2 = 0.f;
    for (int k = 0; k < ch; ++k) {
        float a1 = g_coef[(k * 5 + 0) * NLANE + lane];
        float b1 = g_coef[(k * 5 + 1) * NLANE + lane];
        float P  = g_coef[(k * 5 + 2) * NLANE + lane];
        float Q  = g_coef[(k * 5 + 3) * NLANE + lane];
        float R  = g_coef[(k * 5 + 4) * NLANE + lane];
        float c2n = fmaf(P, c2, fmaf(Q, c1, R));
        c1 = fmaf(a1, c1, b1);
        c2 = c2n;
    }

    if (ch == NCH) {
        const size_t GCS = (size_t)L_DIM * B_DIM * NOUT;
        out[GCS + lane]        = c1;
        out[GCS + 8192 + lane] = c2;
        return;
    }

    float eps  = sigmoidf_fast(__ldg(&bias_eps[n]));
    float rho0 = 2.0f * sigmoidf_fast(__ldg(&bias_final[2 * n]));
    float rho1 = 2.0f * sigmoidf_fast(__ldg(&bias_final[2 * n + 1]));

    const uint2*  qp  = reinterpret_cast<const uint2*>(g_Uh) +
                        (size_t)(ch * CLEN * 16 + b) * 640 + n;
    const __half* ogp = g_Uh + (size_t)(ch * CLEN * 16 + b) * 2560 + 2048 + n;
    float*        gp  = out + (size_t)ch * CLEN * NLANE + lane;

#pragma unroll 4
    for (int l = 0; l < CLEN; ++l) {
        uint2 q = __ldg(qp);
        float2 u = __half22float2(*reinterpret_cast<__half2*>(&q.x));
        float2 f = __half22float2(*reinterpret_cast<__half2*>(&q.y));
        float og = __half2float(__ldg(ogp));
        float c1n = fmaf(c1, f.x, u.x);
        float c2n = fmaf(c2, f.y, (eps + c1) * u.y);
        c1 = c1n; c2 = c2n;
        float t = og * (c1 * rho0 + c2 * rho1);
        float r;
        asm("tanh.approx.f32 %0, %1;" : "=f"(r) : "f"(t));
        *gp = r;
        qp  += 16 * 640;
        ogp += 16 * 2560;
        gp  += NLANE;
    }
}

// ---------------------------------------------------------------------------
extern "C" void kernel_launch(void* const* d_in, const int* in_sizes, int n_in,
                              void* d_out, int out_size) {
    (void)in_sizes; (void)n_in; (void)out_size;
    const float* x          = (const float*)d_in[0];
    const float* weight     = (const float*)d_in[1];
    const float* bias       = (const float*)d_in[2];
    const float* bias_eps   = (const float*)d_in[3];
    const float* bias_final = (const float*)d_in[4];
    float* out = (float*)d_out;

    cudaFuncSetAttribute(gemm_kernel, cudaFuncAttributeMaxDynamicSharedMemorySize, SMEM_DYN);

    prep_kernel<<<8192 + 1280, 256>>>(x, weight);

    dim3 grid(NGEMM / BN, MDIM / BM);   // (20, 128)
    gemm_kernel<<<grid, NTHREADS, SMEM_DYN>>>(bias);

    dim3 p1grid(NLANE / 256, NCH);      // (32, 32)
    scan_pass1<<<p1grid, 256>>>(bias_eps);
    dim3 p2grid(NLANE / 256, NCH + 1);  // (32, 33)
    scan_pass2<<<p2grid, 256>>>(bias_eps, bias_final, out);
}

// round 16
// speedup vs baseline: 1.4725x; 1.0104x over previous
#include <cuda_runtime.h>
#include <cuda_fp16.h>
#include <cstdint>
#include <cstddef>

// ---------------- problem constants ----------------
#define L_DIM 1024
#define B_DIM 16
#define NIN   1024
#define NOUT  512
#define MDIM  16384            // L*B
#define NGEMM 2560             // NOUT*5
#define KGEMM 1024

// ---------------- GEMM tiling ----------------
#define BM 128
#define BN 128
#define KSTAGE 64
#define NSTAGES 3
#define KT (KGEMM / KSTAGE)                 // 16
#define A_BYTES (BM * KSTAGE * 2)           // 16384
#define B_BYTES (BN * KSTAGE * 2)           // 16384
#define STAGE_BYTES (A_BYTES + B_BYTES)     // 32768
#define SMEM_DYN (NSTAGES * STAGE_BYTES)    // 98304
#define NTHREADS 256

// ---------------- scan chunking ----------------
#define NCH   32
#define CLEN  (L_DIM / NCH)                 // 32
#define NLANE 8192                          // B*NOUT

// ---------------- scratch (static, no allocation) ----------------
__device__ __half g_Uh[(size_t)MDIM * NGEMM];   // 80 MB packed fp16 activations
__device__ uint4 g_Xh[(size_t)(MDIM / 16) * (KGEMM / 16) * 32];   // 32 MB A-frag
__device__ uint4 g_Wh[(size_t)(NGEMM / 8) * (KGEMM / 32) * 32];   // 5 MB B-frag
__device__ float4 g_coefv[(size_t)NCH * NLANE]; // (a1,b1,P,Q) per (chunk,lane)
__device__ float  g_coefr[(size_t)NCH * NLANE]; // R per (chunk,lane)

__device__ __forceinline__ float sigmoidf_fast(float x) {
    return 1.0f / (1.0f + __expf(-x));
}
__device__ __forceinline__ uint32_t h2u(float lo, float hi) {
    __half2 h = __floats2half2_rn(lo, hi);
    return *reinterpret_cast<uint32_t*>(&h);
}
__device__ __forceinline__ uint32_t smem_u32(const void* p) {
    return (uint32_t)__cvta_generic_to_shared(p);
}
__device__ __forceinline__ void cp_async16(uint32_t dst, const void* src) {
    asm volatile("cp.async.cg.shared.global [%0], [%1], 16;\n" :: "r"(dst), "l"(src));
}
__device__ __forceinline__ void mma_f16(float4& d, uint4 a, uint32_t b0, uint32_t b1) {
    asm volatile(
        "mma.sync.aligned.m16n8k16.row.col.f32.f16.f16.f32 "
        "{%0,%1,%2,%3}, {%4,%5,%6,%7}, {%8,%9}, {%0,%1,%2,%3};"
        : "+f"(d.x), "+f"(d.y), "+f"(d.z), "+f"(d.w)
        : "r"(a.x), "r"(a.y), "r"(a.z), "r"(a.w), "r"(b0), "r"(b1));
}

// ---------------------------------------------------------------------------
// prep_kernel: fused preround (blocks 0..8191) + permw (blocks 8192..9471)
// ---------------------------------------------------------------------------
__global__ void __launch_bounds__(256)
prep_kernel(const float* __restrict__ x, const float* __restrict__ w) {
    const int tid = threadIdx.x;
    if (blockIdx.x < 8192) {
        __shared__ float sm[16][132];
        const int r16  = blockIdx.x >> 3;
        const int kblk = blockIdx.x & 7;
#pragma unroll
        for (int i = 0; i < 2; i++) {
            int t = i * 256 + tid;
            int row = t >> 5, c4 = t & 31;
            float4 v = *(const float4*)(x + (size_t)(r16 * 16 + row) * KGEMM + kblk * 128 + c4 * 4);
            sm[row][c4 * 4 + 0] = v.x; sm[row][c4 * 4 + 1] = v.y;
            sm[row][c4 * 4 + 2] = v.z; sm[row][c4 * 4 + 3] = v.w;
        }
        __syncthreads();

        int k16l = tid >> 5, lane = tid & 31;
        int g = lane >> 2, tg = lane & 3;
        int c0 = k16l * 16 + tg * 2;
        uint4 o;
        o.x = h2u(sm[g][c0],         sm[g][c0 + 1]);
        o.y = h2u(sm[g + 8][c0],     sm[g + 8][c0 + 1]);
        o.z = h2u(sm[g][c0 + 8],     sm[g][c0 + 9]);
        o.w = h2u(sm[g + 8][c0 + 8], sm[g + 8][c0 + 9]);
        g_Xh[((size_t)r16 * 64 + kblk * 8 + k16l) * 32 + lane] = o;
    } else {
        int t = (blockIdx.x - 8192) * 256 + tid;
        int lane = t & 31;
        int chunk = t >> 5;
        int k32 = chunk & 31, n8 = chunk >> 5;
        int g = lane >> 2, tg = lane & 3;
        int j2 = n8 * 8 + g;
        int j  = (j2 < 2048) ? ((j2 >> 2) * 5 + (j2 & 3)) : ((j2 - 2048) * 5 + 4);
        int k0 = k32 * 32;
        uint4 o;
        o.x = h2u(w[(size_t)(k0 + 2 * tg)      * NGEMM + j], w[(size_t)(k0 + 2 * tg + 1)  * NGEMM + j]);
        o.y = h2u(w[(size_t)(k0 + 2 * tg + 8)  * NGEMM + j], w[(size_t)(k0 + 2 * tg + 9)  * NGEMM + j]);
        o.z = h2u(w[(size_t)(k0 + 2 * tg + 16) * NGEMM + j], w[(size_t)(k0 + 2 * tg + 17) * NGEMM + j]);
        o.w = h2u(w[(size_t)(k0 + 2 * tg + 24) * NGEMM + j], w[(size_t)(k0 + 2 * tg + 25) * NGEMM + j]);
        g_Wh[(size_t)t] = o;
    }
}

// ---------------------------------------------------------------------------
// fp16 mma.sync GEMM: 128x128 tile, 8 warps (4x2), warp tile 32x64, 2 CTAs/SM.
// KSTAGE=64, 3-stage ring, direct half2 epilogue stores.
// ---------------------------------------------------------------------------
__global__ void __launch_bounds__(NTHREADS, 2)
gemm_kernel(const float* __restrict__ bias) {
    extern __shared__ char smraw[];
    const uint32_t sbase = smem_u32(smraw);

    const int tid = threadIdx.x;
    const int wid = tid >> 5, lane = tid & 31;
    const int gid = lane >> 2, tig = lane & 3;
    const int wm = wid >> 1, wn = wid & 1;       // 4 x 2 warps
    const int m0 = blockIdx.y * BM;
    const int n0 = blockIdx.x * BN;

    float4 acc[2][8];
#pragma unroll
    for (int i = 0; i < 2; i++)
#pragma unroll
        for (int j = 0; j < 8; j++) acc[i][j] = make_float4(0.f, 0.f, 0.f, 0.f);

    auto load_stage = [&](int s) {
        uint32_t sb = sbase + (uint32_t)(s % NSTAGES) * STAGE_BYTES;
#pragma unroll
        for (int i = 0; i < 8; i++) {
            int t = i * NTHREADS + tid;           // 0..2047
            if (t < 1024) {                       // A: chunk = r16l*4 + k16l
                int chunk = t >> 5, ln = t & 31;
                int r16l = chunk >> 2, k16l = chunk & 3;
                const uint4* src = g_Xh +
                    ((size_t)((m0 >> 4) + r16l) * 64 + (s * 4 + k16l)) * 32 + ln;
                cp_async16(sb + t * 16, src);
            } else {                              // B: chunk = n8l*2 + k32l
                int jdx = t - 1024;
                int chunk = jdx >> 5, ln = jdx & 31;
                int n8l = chunk >> 1, k32l = chunk & 1;
                const uint4* src = g_Wh +
                    ((size_t)((n0 >> 3) + n8l) * 32 + (s * 2 + k32l)) * 32 + ln;
                cp_async16(sb + A_BYTES + jdx * 16, src);
            }
        }
        asm volatile("cp.async.commit_group;");
    };

    load_stage(0); load_stage(1);

    for (int s = 0; s < KT; ++s) {
        if (s < KT - 1) asm volatile("cp.async.wait_group 1;");
        else            asm volatile("cp.async.wait_group 0;");
        __syncthreads();
        if (s + 2 < KT) load_stage(s + 2);

        const char* As = smraw + (size_t)(s % NSTAGES) * STAGE_BYTES;
        const char* Bs = As + A_BYTES;

#pragma unroll
        for (int k32 = 0; k32 < 2; k32++) {
            uint4 a[2][2];
#pragma unroll
            for (int im = 0; im < 2; im++)
#pragma unroll
                for (int k16 = 0; k16 < 2; k16++)
                    a[im][k16] = *(const uint4*)(As +
                        (((wm * 2 + im) * 4 + k32 * 2 + k16) * 32 + lane) * 16);

#pragma unroll
            for (int jh = 0; jh < 2; jh++) {
                uint4 b[4];
#pragma unroll
                for (int j = 0; j < 4; j++)
                    b[j] = *(const uint4*)(Bs +
                        (((wn * 8 + jh * 4 + j) * 2 + k32) * 32 + lane) * 16);
#pragma unroll
                for (int j = 0; j < 4; j++)
#pragma unroll
                    for (int im = 0; im < 2; im++)
                        mma_f16(acc[im][jh * 4 + j], a[im][0], b[j].x, b[j].y);
#pragma unroll
                for (int j = 0; j < 4; j++)
#pragma unroll
                    for (int im = 0; im < 2; im++)
                        mma_f16(acc[im][jh * 4 + j], a[im][1], b[j].z, b[j].w);
            }
        }
    }

    // ---- epilogue: transform + direct half2 stores ----
#pragma unroll
    for (int im = 0; im < 2; im++) {
        const int row = m0 + wm * 32 + im * 16 + gid;
        __half* r0p = g_Uh + (size_t)row * NGEMM;
        __half* r1p = g_Uh + (size_t)(row + 8) * NGEMM;
#pragma unroll
        for (int jn = 0; jn < 8; jn++) {
            const int col = n0 + wn * 64 + jn * 8 + tig * 2;
            float4 c = acc[im][jn];
            if (col >= 2048) {
                float b0 = __ldg(&bias[col]);
                float b1 = __ldg(&bias[col + 1]);
                c.x = sigmoidf_fast(c.x + b0); c.y = sigmoidf_fast(c.y + b1);
                c.z = sigmoidf_fast(c.z + b0); c.w = sigmoidf_fast(c.w + b1);
            } else if (col & 2) {
                int n = col >> 2;
                float b0 = __ldg(&bias[1024 + n]);
                float b1 = __ldg(&bias[1536 + n]);
                c.x = sigmoidf_fast(c.x + b0); c.y = sigmoidf_fast(c.y + b1);
                c.z = sigmoidf_fast(c.z + b0); c.w = sigmoidf_fast(c.w + b1);
            }
            *(__half2*)(r0p + col) = __floats2half2_rn(c.x, c.y);
            *(__half2*)(r1p + col) = __floats2half2_rn(c.z, c.w);
        }
    }
}

// ---------------------------------------------------------------------------
// Scan pass 1: per-(lane, chunk) transfer coefficients (fp16 in, fp32 math)
//   c1(t) = a1*c1_0 + b1 ;  c2(t) = P*c2_0 + Q*c1_0 + R
// ---------------------------------------------------------------------------
__global__ void __launch_bounds__(256)
scan_pass1(const float* __restrict__ bias_eps) {
    int lane = blockIdx.x * 256 + threadIdx.x;
    int ch   = blockIdx.y;
    int n = lane & (NOUT - 1);
    int b = lane >> 9;

    float eps = sigmoidf_fast(__ldg(&bias_eps[n]));

    float a1 = 1.f, b1 = 0.f, P = 1.f, Q = 0.f, R = 0.f;

    const uint2* qp = reinterpret_cast<const uint2*>(g_Uh) +
                      (size_t)(ch * CLEN * 16 + b) * 640 + n;

#pragma unroll 8
    for (int l = 0; l < CLEN; ++l) {
        uint2 q = __ldg(qp);
        float2 u = __half22float2(*reinterpret_cast<__half2*>(&q.x));
        float2 f = __half22float2(*reinterpret_cast<__half2*>(&q.y));
        Q = fmaf(Q, f.y, a1 * u.y);
        R = fmaf(R, f.y, (eps + b1) * u.y);
        P = P * f.y;
        b1 = fmaf(b1, f.x, u.x);
        a1 = a1 * f.x;
        qp += 16 * 640;
    }
    g_coefv[(size_t)ch * NLANE + lane] = make_float4(a1, b1, P, Q);
    g_coefr[(size_t)ch * NLANE + lane] = R;
}

// ---------------------------------------------------------------------------
// Scan pass 2 (combine fused): prologue chains packed coefs over chunks < ch,
// then replays the chunk. Row ch == NCH writes the final carries only.
// ---------------------------------------------------------------------------
__global__ void __launch_bounds__(256)
scan_pass2(const float* __restrict__ bias_eps, const float* __restrict__ bias_final,
           float* __restrict__ out) {
    int lane = blockIdx.x * 256 + threadIdx.x;
    int ch   = blockIdx.y;           // 0..NCH
    int n = lane & (NOUT - 1);
    int b = lane >> 9;

    float c1 = 0.f, c2 = 0.f;
    for (int k = 0; k < ch; ++k) {
        float4 v = g_coefv[(size_t)k * NLANE + lane];   // (a1,b1,P,Q)
        float  R = g_coefr[(size_t)k * NLANE + lane];
        float c2n = fmaf(v.z, c2, fmaf(v.w, c1, R));
        c1 = fmaf(v.x, c1, v.y);
        c2 = c2n;
    }

    if (ch == NCH) {
        const size_t GCS = (size_t)L_DIM * B_DIM * NOUT;
        out[GCS + lane]        = c1;
        out[GCS + 8192 + lane] = c2;
        return;
    }

    float eps  = sigmoidf_fast(__ldg(&bias_eps[n]));
    float rho0 = 2.0f * sigmoidf_fast(__ldg(&bias_final[2 * n]));
    float rho1 = 2.0f * sigmoidf_fast(__ldg(&bias_final[2 * n + 1]));

    const uint2*  qp  = reinterpret_cast<const uint2*>(g_Uh) +
                        (size_t)(ch * CLEN * 16 + b) * 640 + n;
    const __half* ogp = g_Uh + (size_t)(ch * CLEN * 16 + b) * 2560 + 2048 + n;
    float*        gp  = out + (size_t)ch * CLEN * NLANE + lane;

#pragma unroll 8
    for (int l = 0; l < CLEN; ++l) {
        uint2 q = __ldg(qp);
        float2 u = __half22float2(*reinterpret_cast<__half2*>(&q.x));
        float2 f = __half22float2(*reinterpret_cast<__half2*>(&q.y));
        float og = __half2float(__ldg(ogp));
        float c1n = fmaf(c1, f.x, u.x);
        float c2n = fmaf(c2, f.y, (eps + c1) * u.y);
        c1 = c1n; c2 = c2n;
        float t = og * (c1 * rho0 + c2 * rho1);
        float r;
        asm("tanh.approx.f32 %0, %1;" : "=f"(r) : "f"(t));
        *gp = r;
        qp  += 16 * 640;
        ogp += 16 * 2560;
        gp  += NLANE;
    }
}

// ---------------------------------------------------------------------------
extern "C" void kernel_launch(void* const* d_in, const int* in_sizes, int n_in,
                              void* d_out, int out_size) {
    (void)in_sizes; (void)n_in; (void)out_size;
    const float* x          = (const float*)d_in[0];
    const float* weight     = (const float*)d_in[1];
    const float* bias       = (const float*)d_in[2];
    const float* bias_eps   = (const float*)d_in[3];
    const float* bias_final = (const float*)d_in[4];
    float* out = (float*)d_out;

    cudaFuncSetAttribute(gemm_kernel, cudaFuncAttributeMaxDynamicSharedMemorySize, SMEM_DYN);

    prep_kernel<<<8192 + 1280, 256>>>(x, weight);

    dim3 grid(NGEMM / BN, MDIM / BM);   // (20, 128)
    gemm_kernel<<<grid, NTHREADS, SMEM_DYN>>>(bias);

    dim3 p1grid(NLANE / 256, NCH);      // (32, 32)
    scan_pass1<<<p1grid, 256>>>(bias_eps);
    dim3 p2grid(NLANE / 256, NCH + 1);  // (32, 33)
    scan_pass2<<<p2grid, 256>>>(bias_eps, bias_final, out);
}

// round 17
// speedup vs baseline: 1.4755x; 1.0021x over previous
#include <cuda_runtime.h>
#include <cuda_fp16.h>
#include <cstdint>
#include <cstddef>

// ---------------- problem constants ----------------
#define L_DIM 1024
#define B_DIM 16
#define NIN   1024
#define NOUT  512
#define MDIM  16384            // L*B
#define NGEMM 2560             // NOUT*5
#define KGEMM 1024

// ---------------- GEMM tiling ----------------
#define BM 128
#define BN 128
#define KSTAGE 64
#define NSTAGES 3
#define KT (KGEMM / KSTAGE)                 // 16
#define A_BYTES (BM * KSTAGE * 2)           // 16384
#define B_BYTES (BN * KSTAGE * 2)           // 16384
#define STAGE_BYTES (A_BYTES + B_BYTES)     // 32768
#define SMEM_DYN (NSTAGES * STAGE_BYTES)    // 98304
#define NTHREADS 256

// ---------------- scan chunking ----------------
#define NCH   32
#define CLEN  (L_DIM / NCH)                 // 32
#define NLANE 8192                          // B*NOUT

// ---------------- scratch (static, no allocation) ----------------
__device__ __half g_Uh[(size_t)MDIM * NGEMM];   // 80 MB packed fp16 activations
__device__ uint4 g_Xh[(size_t)(MDIM / 16) * (KGEMM / 16) * 32];   // 32 MB A-frag
__device__ uint4 g_Wh[(size_t)(NGEMM / 8) * (KGEMM / 32) * 32];   // 5 MB B-frag
__device__ float4 g_coefv[(size_t)NCH * NLANE]; // (a1,b1,P,Q) per (chunk,lane)
__device__ float  g_coefr[(size_t)NCH * NLANE]; // R per (chunk,lane)

__device__ __forceinline__ float sigmoidf_fast(float x) {
    return 1.0f / (1.0f + __expf(-x));
}
__device__ __forceinline__ uint32_t h2u(float lo, float hi) {
    __half2 h = __floats2half2_rn(lo, hi);
    return *reinterpret_cast<uint32_t*>(&h);
}
__device__ __forceinline__ uint32_t smem_u32(const void* p) {
    return (uint32_t)__cvta_generic_to_shared(p);
}
__device__ __forceinline__ void cp_async16(uint32_t dst, const void* src) {
    asm volatile("cp.async.cg.shared.global [%0], [%1], 16;\n" :: "r"(dst), "l"(src));
}
__device__ __forceinline__ void mma_f16(float4& d, uint4 a, uint32_t b0, uint32_t b1) {
    asm volatile(
        "mma.sync.aligned.m16n8k16.row.col.f32.f16.f16.f32 "
        "{%0,%1,%2,%3}, {%4,%5,%6,%7}, {%8,%9}, {%0,%1,%2,%3};"
        : "+f"(d.x), "+f"(d.y), "+f"(d.z), "+f"(d.w)
        : "r"(a.x), "r"(a.y), "r"(a.z), "r"(a.w), "r"(b0), "r"(b1));
}
// PDL controls
__device__ __forceinline__ void pdl_wait()    { asm volatile("griddepcontrol.wait;" ::: "memory"); }
__device__ __forceinline__ void pdl_trigger() { asm volatile("griddepcontrol.launch_dependents;" ::: "memory"); }

// ---------------------------------------------------------------------------
// prep_kernel: fused preround (blocks 0..8191) + permw (blocks 8192..9471)
// ---------------------------------------------------------------------------
__global__ void __launch_bounds__(256)
prep_kernel(const float* __restrict__ x, const float* __restrict__ w) {
    const int tid = threadIdx.x;
    if (blockIdx.x < 8192) {
        __shared__ float sm[16][132];
        const int r16  = blockIdx.x >> 3;
        const int kblk = blockIdx.x & 7;
#pragma unroll
        for (int i = 0; i < 2; i++) {
            int t = i * 256 + tid;
            int row = t >> 5, c4 = t & 31;
            float4 v = *(const float4*)(x + (size_t)(r16 * 16 + row) * KGEMM + kblk * 128 + c4 * 4);
            sm[row][c4 * 4 + 0] = v.x; sm[row][c4 * 4 + 1] = v.y;
            sm[row][c4 * 4 + 2] = v.z; sm[row][c4 * 4 + 3] = v.w;
        }
        __syncthreads();

        int k16l = tid >> 5, lane = tid & 31;
        int g = lane >> 2, tg = lane & 3;
        int c0 = k16l * 16 + tg * 2;
        uint4 o;
        o.x = h2u(sm[g][c0],         sm[g][c0 + 1]);
        o.y = h2u(sm[g + 8][c0],     sm[g + 8][c0 + 1]);
        o.z = h2u(sm[g][c0 + 8],     sm[g][c0 + 9]);
        o.w = h2u(sm[g + 8][c0 + 8], sm[g + 8][c0 + 9]);
        g_Xh[((size_t)r16 * 64 + kblk * 8 + k16l) * 32 + lane] = o;
    } else {
        int t = (blockIdx.x - 8192) * 256 + tid;
        int lane = t & 31;
        int chunk = t >> 5;
        int k32 = chunk & 31, n8 = chunk >> 5;
        int g = lane >> 2, tg = lane & 3;
        int j2 = n8 * 8 + g;
        int j  = (j2 < 2048) ? ((j2 >> 2) * 5 + (j2 & 3)) : ((j2 - 2048) * 5 + 4);
        int k0 = k32 * 32;
        uint4 o;
        o.x = h2u(w[(size_t)(k0 + 2 * tg)      * NGEMM + j], w[(size_t)(k0 + 2 * tg + 1)  * NGEMM + j]);
        o.y = h2u(w[(size_t)(k0 + 2 * tg + 8)  * NGEMM + j], w[(size_t)(k0 + 2 * tg + 9)  * NGEMM + j]);
        o.z = h2u(w[(size_t)(k0 + 2 * tg + 16) * NGEMM + j], w[(size_t)(k0 + 2 * tg + 17) * NGEMM + j]);
        o.w = h2u(w[(size_t)(k0 + 2 * tg + 24) * NGEMM + j], w[(size_t)(k0 + 2 * tg + 25) * NGEMM + j]);
        g_Wh[(size_t)t] = o;
    }
    pdl_trigger();
}

// ---------------------------------------------------------------------------
// fp16 mma.sync GEMM: 128x128 tile, 8 warps (4x2), warp tile 32x64, 2 CTAs/SM.
// KSTAGE=64, 3-stage ring, direct half2 epilogue stores. PDL producer+consumer.
// ---------------------------------------------------------------------------
__global__ void __launch_bounds__(NTHREADS, 2)
gemm_kernel(const float* __restrict__ bias) {
    extern __shared__ char smraw[];
    const uint32_t sbase = smem_u32(smraw);

    const int tid = threadIdx.x;
    const int wid = tid >> 5, lane = tid & 31;
    const int gid = lane >> 2, tig = lane & 3;
    const int wm = wid >> 1, wn = wid & 1;       // 4 x 2 warps
    const int m0 = blockIdx.y * BM;
    const int n0 = blockIdx.x * BN;

    float4 acc[2][8];
#pragma unroll
    for (int i = 0; i < 2; i++)
#pragma unroll
        for (int j = 0; j < 8; j++) acc[i][j] = make_float4(0.f, 0.f, 0.f, 0.f);

    auto load_stage = [&](int s) {
        uint32_t sb = sbase + (uint32_t)(s % NSTAGES) * STAGE_BYTES;
#pragma unroll
        for (int i = 0; i < 8; i++) {
            int t = i * NTHREADS + tid;           // 0..2047
            if (t < 1024) {                       // A: chunk = r16l*4 + k16l
                int chunk = t >> 5, ln = t & 31;
                int r16l = chunk >> 2, k16l = chunk & 3;
                const uint4* src = g_Xh +
                    ((size_t)((m0 >> 4) + r16l) * 64 + (s * 4 + k16l)) * 32 + ln;
                cp_async16(sb + t * 16, src);
            } else {                              // B: chunk = n8l*2 + k32l
                int jdx = t - 1024;
                int chunk = jdx >> 5, ln = jdx & 31;
                int n8l = chunk >> 1, k32l = chunk & 1;
                const uint4* src = g_Wh +
                    ((size_t)((n0 >> 3) + n8l) * 32 + (s * 2 + k32l)) * 32 + ln;
                cp_async16(sb + A_BYTES + jdx * 16, src);
            }
        }
        asm volatile("cp.async.commit_group;");
    };

    pdl_wait();            // g_Xh / g_Wh ready (prep_kernel)
    load_stage(0); load_stage(1);

    for (int s = 0; s < KT; ++s) {
        if (s < KT - 1) asm volatile("cp.async.wait_group 1;");
        else            asm volatile("cp.async.wait_group 0;");
        __syncthreads();
        if (s + 2 < KT) load_stage(s + 2);

        const char* As = smraw + (size_t)(s % NSTAGES) * STAGE_BYTES;
        const char* Bs = As + A_BYTES;

#pragma unroll
        for (int k32 = 0; k32 < 2; k32++) {
            uint4 a[2][2];
#pragma unroll
            for (int im = 0; im < 2; im++)
#pragma unroll
                for (int k16 = 0; k16 < 2; k16++)
                    a[im][k16] = *(const uint4*)(As +
                        (((wm * 2 + im) * 4 + k32 * 2 + k16) * 32 + lane) * 16);

#pragma unroll
            for (int jh = 0; jh < 2; jh++) {
                uint4 b[4];
#pragma unroll
                for (int j = 0; j < 4; j++)
                    b[j] = *(const uint4*)(Bs +
                        (((wn * 8 + jh * 4 + j) * 2 + k32) * 32 + lane) * 16);
#pragma unroll
                for (int j = 0; j < 4; j++)
#pragma unroll
                    for (int im = 0; im < 2; im++)
                        mma_f16(acc[im][jh * 4 + j], a[im][0], b[j].x, b[j].y);
#pragma unroll
                for (int j = 0; j < 4; j++)
#pragma unroll
                    for (int im = 0; im < 2; im++)
                        mma_f16(acc[im][jh * 4 + j], a[im][1], b[j].z, b[j].w);
            }
        }
    }

    // ---- epilogue: transform + direct half2 stores ----
#pragma unroll
    for (int im = 0; im < 2; im++) {
        const int row = m0 + wm * 32 + im * 16 + gid;
        __half* r0p = g_Uh + (size_t)row * NGEMM;
        __half* r1p = g_Uh + (size_t)(row + 8) * NGEMM;
#pragma unroll
        for (int jn = 0; jn < 8; jn++) {
            const int col = n0 + wn * 64 + jn * 8 + tig * 2;
            float4 c = acc[im][jn];
            if (col >= 2048) {
                float b0 = __ldg(&bias[col]);
                float b1 = __ldg(&bias[col + 1]);
                c.x = sigmoidf_fast(c.x + b0); c.y = sigmoidf_fast(c.y + b1);
                c.z = sigmoidf_fast(c.z + b0); c.w = sigmoidf_fast(c.w + b1);
            } else if (col & 2) {
                int n = col >> 2;
                float b0 = __ldg(&bias[1024 + n]);
                float b1 = __ldg(&bias[1536 + n]);
                c.x = sigmoidf_fast(c.x + b0); c.y = sigmoidf_fast(c.y + b1);
                c.z = sigmoidf_fast(c.z + b0); c.w = sigmoidf_fast(c.w + b1);
            }
            *(__half2*)(r0p + col) = __floats2half2_rn(c.x, c.y);
            *(__half2*)(r1p + col) = __floats2half2_rn(c.z, c.w);
        }
    }
    pdl_trigger();
}

// ---------------------------------------------------------------------------
// Scan pass 1: per-(lane, chunk) transfer coefficients (fp16 in, fp32 math)
// ---------------------------------------------------------------------------
__global__ void __launch_bounds__(256)
scan_pass1(const float* __restrict__ bias_eps) {
    int lane = blockIdx.x * 256 + threadIdx.x;
    int ch   = blockIdx.y;
    int n = lane & (NOUT - 1);
    int b = lane >> 9;

    float eps = sigmoidf_fast(__ldg(&bias_eps[n]));

    float a1 = 1.f, b1 = 0.f, P = 1.f, Q = 0.f, R = 0.f;

    const uint2* qp = reinterpret_cast<const uint2*>(g_Uh) +
                      (size_t)(ch * CLEN * 16 + b) * 640 + n;

    pdl_wait();            // g_Uh ready (gemm_kernel)
#pragma unroll 8
    for (int l = 0; l < CLEN; ++l) {
        uint2 q = __ldg(qp);
        float2 u = __half22float2(*reinterpret_cast<__half2*>(&q.x));
        float2 f = __half22float2(*reinterpret_cast<__half2*>(&q.y));
        Q = fmaf(Q, f.y, a1 * u.y);
        R = fmaf(R, f.y, (eps + b1) * u.y);
        P = P * f.y;
        b1 = fmaf(b1, f.x, u.x);
        a1 = a1 * f.x;
        qp += 16 * 640;
    }
    g_coefv[(size_t)ch * NLANE + lane] = make_float4(a1, b1, P, Q);
    g_coefr[(size_t)ch * NLANE + lane] = R;
    pdl_trigger();
}

// ---------------------------------------------------------------------------
// Scan pass 2 (combine fused): prologue chains packed coefs over chunks < ch,
// then replays the chunk. Row ch == NCH writes the final carries only.
// ---------------------------------------------------------------------------
__global__ void __launch_bounds__(256)
scan_pass2(const float* __restrict__ bias_eps, const float* __restrict__ bias_final,
           float* __restrict__ out) {
    int lane = blockIdx.x * 256 + threadIdx.x;
    int ch   = blockIdx.y;           // 0..NCH
    int n = lane & (NOUT - 1);
    int b = lane >> 9;

    float eps  = sigmoidf_fast(__ldg(&bias_eps[n]));
    float rho0 = 2.0f * sigmoidf_fast(__ldg(&bias_final[2 * n]));
    float rho1 = 2.0f * sigmoidf_fast(__ldg(&bias_final[2 * n + 1]));

    pdl_wait();            // g_coefv / g_coefr ready (scan_pass1)

    float c1 = 0.f, c2 = 0.f;
    for (int k = 0; k < ch; ++k) {
        float4 v = g_coefv[(size_t)k * NLANE + lane];   // (a1,b1,P,Q)
        float  R = g_coefr[(size_t)k * NLANE + lane];
        float c2n = fmaf(v.z, c2, fmaf(v.w, c1, R));
        c1 = fmaf(v.x, c1, v.y);
        c2 = c2n;
    }

    if (ch == NCH) {
        const size_t GCS = (size_t)L_DIM * B_DIM * NOUT;
        out[GCS + lane]        = c1;
        out[GCS + 8192 + lane] = c2;
        return;
    }

    const uint2*  qp  = reinterpret_cast<const uint2*>(g_Uh) +
                        (size_t)(ch * CLEN * 16 + b) * 640 + n;
    const __half* ogp = g_Uh + (size_t)(ch * CLEN * 16 + b) * 2560 + 2048 + n;
    float*        gp  = out + (size_t)ch * CLEN * NLANE + lane;

#pragma unroll 8
    for (int l = 0; l < CLEN; ++l) {
        uint2 q = __ldg(qp);
        float2 u = __half22float2(*reinterpret_cast<__half2*>(&q.x));
        float2 f = __half22float2(*reinterpret_cast<__half2*>(&q.y));
        float og = __half2float(__ldg(ogp));
        float c1n = fmaf(c1, f.x, u.x);
        float c2n = fmaf(c2, f.y, (eps + c1) * u.y);
        c1 = c1n; c2 = c2n;
        float t = og * (c1 * rho0 + c2 * rho1);
        float r;
        asm("tanh.approx.f32 %0, %1;" : "=f"(r) : "f"(t));
        *gp = r;
        qp  += 16 * 640;
        ogp += 16 * 2560;
        gp  += NLANE;
    }
}

// ---------------------------------------------------------------------------
static void launch_pdl(void* func, dim3 grid, dim3 block, size_t smem,
                       void** args) {
    cudaLaunchConfig_t cfg = {};
    cfg.gridDim = grid;
    cfg.blockDim = block;
    cfg.dynamicSmemBytes = smem;
    cfg.stream = 0;
    cudaLaunchAttribute at[1];
    at[0].id = cudaLaunchAttributeProgrammaticStreamSerialization;
    at[0].val.programmaticStreamSerializationAllowed = 1;
    cfg.attrs = at;
    cfg.numAttrs = 1;
    cudaLaunchKernelExC(&cfg, func, args);
}

extern "C" void kernel_launch(void* const* d_in, const int* in_sizes, int n_in,
                              void* d_out, int out_size) {
    (void)in_sizes; (void)n_in; (void)out_size;
    const float* x          = (const float*)d_in[0];
    const float* weight     = (const float*)d_in[1];
    const float* bias       = (const float*)d_in[2];
    const float* bias_eps   = (const float*)d_in[3];
    const float* bias_final = (const float*)d_in[4];
    float* out = (float*)d_out;

    cudaFuncSetAttribute(gemm_kernel, cudaFuncAttributeMaxDynamicSharedMemorySize, SMEM_DYN);

    prep_kernel<<<8192 + 1280, 256>>>(x, weight);

    {   // GEMM with PDL (overlaps prep tail)
        void* args[] = { (void*)&bias };
        launch_pdl((void*)gemm_kernel, dim3(NGEMM / BN, MDIM / BM), dim3(NTHREADS),
                   SMEM_DYN, args);
    }
    {   // pass1 with PDL (overlaps gemm tail)
        void* args[] = { (void*)&bias_eps };
        launch_pdl((void*)scan_pass1, dim3(NLANE / 256, NCH), dim3(256), 0, args);
    }
    {   // pass2 with PDL (overlaps pass1 tail)
        void* args[] = { (void*)&bias_eps, (void*)&bias_final, (void*)&out };
        launch_pdl((void*)scan_pass2, dim3(NLANE / 256, NCH + 1), dim3(256), 0, args);
    }
}